// round 2
// baseline (speedup 1.0000x reference)
#include <cuda_runtime.h>
#include <math.h>

#define NATOMS 8000
#define NEDGES 100000
#define NTRIP  500000
#define NGRAPHS 64
#define HD 128
#define NR 6
#define NSNR 42
#define NB 8
#define NBLK 6

// ---------------- device scratch (no allocation allowed) ----------------
__device__ float g_X   [NEDGES*HD];
__device__ float g_XS  [NEDGES*HD];
__device__ float g_XJI [NEDGES*HD];
__device__ float g_XKJ [NEDGES*HD];
__device__ float g_T1  [NEDGES*HD];
__device__ float g_RBFP[NEDGES*HD];
__device__ float g_SBFP[NTRIP*NB];
__device__ float g_G   [(size_t)NEDGES*NB*HD];   // also reused as [E,384] embed input
__device__ float g_WT  [HD*NB*HD];
__device__ float g_ATOM [NATOMS*HD];
__device__ float g_ATOM2[NATOMS*HD];

__device__ __forceinline__ float silu(float x) { return x / (1.0f + expf(-x)); }

// ---------------- generic fused GEMM: C = epi(A[M,K] @ B[K,N] + bias) ----------------
// epi: (optional silu) -> (optional *mulv) -> (optional +addv)
__global__ __launch_bounds__(256) void gemm_k(
    const float* __restrict__ A, const float* __restrict__ B,
    const float* __restrict__ bias, const float* __restrict__ addv,
    const float* __restrict__ mulv, float* __restrict__ C,
    int M, int N, int K, int act)
{
    __shared__ float As[8][128];
    __shared__ float Bs[8][128];

    const int bM = blockIdx.y * 128;
    const int bN = blockIdx.x * 128;
    const int tid = threadIdx.x;
    const int tr = tid >> 4;          // 0..15
    const int tc = tid & 15;          // 0..15

    const int aRow = tid >> 1, aCol = (tid & 1) * 4;
    const int bRow = tid >> 5, bCol = (tid & 31) * 4;

    float acc[8][8];
#pragma unroll
    for (int u = 0; u < 8; u++)
#pragma unroll
        for (int v = 0; v < 8; v++) acc[u][v] = 0.0f;

    for (int k0 = 0; k0 < K; k0 += 8) {
        float4 av;
        if (bM + aRow < M)
            av = *(const float4*)(A + (size_t)(bM + aRow) * K + k0 + aCol);
        else
            av = make_float4(0.f, 0.f, 0.f, 0.f);
        As[aCol + 0][aRow] = av.x;
        As[aCol + 1][aRow] = av.y;
        As[aCol + 2][aRow] = av.z;
        As[aCol + 3][aRow] = av.w;

        float4 bv = *(const float4*)(B + (size_t)(k0 + bRow) * N + bN + bCol);
        *(float4*)&Bs[bRow][bCol] = bv;
        __syncthreads();

#pragma unroll
        for (int kk = 0; kk < 8; kk++) {
            float4 a0 = *(float4*)&As[kk][tr * 8];
            float4 a1 = *(float4*)&As[kk][tr * 8 + 4];
            float4 b0 = *(float4*)&Bs[kk][tc * 8];
            float4 b1 = *(float4*)&Bs[kk][tc * 8 + 4];
            float ar[8] = {a0.x, a0.y, a0.z, a0.w, a1.x, a1.y, a1.z, a1.w};
            float br[8] = {b0.x, b0.y, b0.z, b0.w, b1.x, b1.y, b1.z, b1.w};
#pragma unroll
            for (int u = 0; u < 8; u++)
#pragma unroll
                for (int v = 0; v < 8; v++) acc[u][v] += ar[u] * br[v];
        }
        __syncthreads();
    }

    float bvals[8];
#pragma unroll
    for (int v = 0; v < 8; v++) bvals[v] = bias ? bias[bN + tc * 8 + v] : 0.0f;

#pragma unroll
    for (int u = 0; u < 8; u++) {
        int row = bM + tr * 8 + u;
        if (row >= M) break;
        size_t base = (size_t)row * N + bN + tc * 8;
#pragma unroll
        for (int q = 0; q < 2; q++) {
            float r[4];
#pragma unroll
            for (int c = 0; c < 4; c++) {
                float v = acc[u][q * 4 + c] + bvals[q * 4 + c];
                if (act) v = silu(v);
                r[c] = v;
            }
            if (mulv) {
                float4 mv = *(const float4*)(mulv + base + q * 4);
                r[0] *= mv.x; r[1] *= mv.y; r[2] *= mv.z; r[3] *= mv.w;
            }
            if (addv) {
                float4 avv = *(const float4*)(addv + base + q * 4);
                r[0] += avv.x; r[1] += avv.y; r[2] += avv.z; r[3] += avv.w;
            }
            *(float4*)(C + base + q * 4) = make_float4(r[0], r[1], r[2], r[3]);
        }
    }
}

// ---------------- embedding: build A_emb[E,384] = [h_i | h_j | silu(rbf@W+b)] ----------------
__global__ void embed_fill_k(const int* __restrict__ z, const int* __restrict__ ei,
                             const int* __restrict__ ej, const float* __restrict__ rbf,
                             const float* __restrict__ emb_table,
                             const float* __restrict__ erw, const float* __restrict__ erb,
                             float* __restrict__ Aemb)
{
    int e = blockIdx.x, h = threadIdx.x;
    int zi = z[ei[e]], zj = z[ej[e]];
    float s = erb[h];
    const float* rr = rbf + (size_t)e * NR;
#pragma unroll
    for (int r = 0; r < NR; r++) s += rr[r] * erw[r * HD + h];
    size_t base = (size_t)e * (3 * HD);
    Aemb[base + h]           = emb_table[(size_t)zi * HD + h];
    Aemb[base + HD + h]      = emb_table[(size_t)zj * HD + h];
    Aemb[base + 2 * HD + h]  = silu(s);
}

// ---------------- rbf projection: RBFP[e,h] = rbf[e,:] @ W[:,h] ----------------
__global__ void rbfp_k(const float* __restrict__ rbf, const float* __restrict__ w,
                       float* __restrict__ outp)
{
    int e = blockIdx.x, h = threadIdx.x;
    const float* rr = rbf + (size_t)e * NR;
    float s = 0.f;
#pragma unroll
    for (int r = 0; r < NR; r++) s += rr[r] * w[r * HD + h];
    outp[(size_t)e * HD + h] = s;
}

// ---------------- sbf projection: SBFP[t,j] = sbf[t,:42] @ W[:42,j] ----------------
__global__ void sbfp_k(const float* __restrict__ sbf, const float* __restrict__ w,
                       float* __restrict__ outp)
{
    __shared__ float ws[NSNR * NB];
    for (int idx = threadIdx.x; idx < NSNR * NB; idx += blockDim.x) ws[idx] = w[idx];
    __syncthreads();
    int t = blockIdx.x * blockDim.x + threadIdx.x;
    if (t >= NTRIP) return;
    const float* sr = sbf + (size_t)t * NSNR;
    float acc[NB];
#pragma unroll
    for (int j = 0; j < NB; j++) acc[j] = 0.f;
    for (int r = 0; r < NSNR; r++) {
        float s = sr[r];
#pragma unroll
        for (int j = 0; j < NB; j++) acc[j] += s * ws[r * NB + j];
    }
    float* op = outp + (size_t)t * NB;
#pragma unroll
    for (int j = 0; j < NB; j++) op[j] = acc[j];
}

// ---------------- W transpose: WT[l*1024 + j*128 + i] = W[i*1024 + j*128 + l] ----------------
__global__ void wt_k(const float* __restrict__ W, float* __restrict__ WT)
{
    int idx = blockIdx.x * blockDim.x + threadIdx.x;   // 131072 elems
    int l = idx >> 10;
    int rest = idx & 1023;
    int j = rest >> 7;
    int i = rest & 127;
    WT[idx] = W[(size_t)i * (NB * HD) + j * HD + l];
}

// ---------------- triplet scatter: M[idx_ji[w],:] += sum_j sbf_p[w,j] * G[idx_kj[w], j, :] ----
__global__ __launch_bounds__(256) void trip_k(
    const float* __restrict__ G, const float* __restrict__ sbfp,
    const int* __restrict__ idx_kj, const int* __restrict__ idx_ji,
    float* __restrict__ Mo)
{
    int w = blockIdx.x * (blockDim.x >> 5) + (threadIdx.x >> 5);
    if (w >= NTRIP) return;
    int lane = threadIdx.x & 31;
    int kj = idx_kj[w], ji = idx_ji[w];
    float sv = (lane < NB) ? sbfp[(size_t)w * NB + lane] : 0.f;
    const float* gr = G + (size_t)kj * (NB * HD) + lane * 4;
    float4 acc = make_float4(0.f, 0.f, 0.f, 0.f);
#pragma unroll
    for (int j = 0; j < NB; j++) {
        float s = __shfl_sync(0xffffffffu, sv, j);
        float4 g = *(const float4*)(gr + j * HD);
        acc.x += s * g.x; acc.y += s * g.y; acc.z += s * g.z; acc.w += s * g.w;
    }
    float* mo = Mo + (size_t)ji * HD + lane * 4;
    atomicAdd(mo + 0, acc.x);
    atomicAdd(mo + 1, acc.y);
    atomicAdd(mo + 2, acc.z);
    atomicAdd(mo + 3, acc.w);
}

// ---------------- out-block edge scatter: ATOM[i[e],h] += (rbf@orw)[h] * x[e,h] ------------
__global__ void edge_scatter_k(const float* __restrict__ rbf, const float* __restrict__ orw,
                               const float* __restrict__ x, const int* __restrict__ ei,
                               float* __restrict__ atom)
{
    int e = blockIdx.x, h = threadIdx.x;
    const float* rr = rbf + (size_t)e * NR;
    float rp = 0.f;
#pragma unroll
    for (int r = 0; r < NR; r++) rp += rr[r] * orw[r * HD + h];
    float v = rp * x[(size_t)e * HD + h];
    atomicAdd(&atom[(size_t)ei[e] * HD + h], v);
}

// ---------------- final per-atom dot + graph segment sum ----------------
__global__ void dot_k(const float* __restrict__ atom2, const float* __restrict__ ow,
                      const int* __restrict__ batch, float* __restrict__ out)
{
    int a = blockIdx.x * (blockDim.x >> 5) + (threadIdx.x >> 5);
    if (a >= NATOMS) return;
    int lane = threadIdx.x & 31;
    const float* ar = atom2 + (size_t)a * HD + lane * 4;
    const float* wr = ow + lane * 4;
    float s = ar[0] * wr[0] + ar[1] * wr[1] + ar[2] * wr[2] + ar[3] * wr[3];
#pragma unroll
    for (int o = 16; o > 0; o >>= 1) s += __shfl_down_sync(0xffffffffu, s, o);
    if (lane == 0) atomicAdd(&out[batch[a]], s);
}

// ==========================================================================================
extern "C" void kernel_launch(void* const* d_in, const int* in_sizes, int n_in,
                              void* d_out, int out_size)
{
    const int*   z        = (const int*)  d_in[0];
    const float* rbf      = (const float*)d_in[1];
    const float* sbf      = (const float*)d_in[2];
    const int*   ei       = (const int*)  d_in[3];
    const int*   ej       = (const int*)  d_in[4];
    const int*   idx_kj   = (const int*)  d_in[5];
    const int*   idx_ji   = (const int*)  d_in[6];
    const int*   batch    = (const int*)  d_in[7];
    const float* emb_table= (const float*)d_in[8];
    const float* emb_rbf_w= (const float*)d_in[9];
    const float* emb_rbf_b= (const float*)d_in[10];
    const float* emb_w    = (const float*)d_in[11];
    const float* emb_b    = (const float*)d_in[12];
    const float* int_rbf_w= (const float*)d_in[13];
    const float* int_sbf_w= (const float*)d_in[14];
    const float* int_kj_w = (const float*)d_in[15];
    const float* int_kj_b = (const float*)d_in[16];
    const float* int_ji_w = (const float*)d_in[17];
    const float* int_ji_b = (const float*)d_in[18];
    const float* int_W    = (const float*)d_in[19];
    const float* int_bef_w= (const float*)d_in[20];
    const float* int_bef_b= (const float*)d_in[21];
    const float* int_lin_w= (const float*)d_in[22];
    const float* int_lin_b= (const float*)d_in[23];
    const float* int_aft_w= (const float*)d_in[24];
    const float* int_aft_b= (const float*)d_in[25];
    const float* out_rbf_w= (const float*)d_in[26];
    const float* out_lins_w=(const float*)d_in[27];
    const float* out_lins_b=(const float*)d_in[28];
    const float* out_w    = (const float*)d_in[29];
    float* out = (float*)d_out;

    float *X, *XS, *XJI, *XKJ, *T1, *RBFP, *SBFP, *G, *WT, *ATOM, *ATOM2;
    cudaGetSymbolAddress((void**)&X,    g_X);
    cudaGetSymbolAddress((void**)&XS,   g_XS);
    cudaGetSymbolAddress((void**)&XJI,  g_XJI);
    cudaGetSymbolAddress((void**)&XKJ,  g_XKJ);
    cudaGetSymbolAddress((void**)&T1,   g_T1);
    cudaGetSymbolAddress((void**)&RBFP, g_RBFP);
    cudaGetSymbolAddress((void**)&SBFP, g_SBFP);
    cudaGetSymbolAddress((void**)&G,    g_G);
    cudaGetSymbolAddress((void**)&WT,   g_WT);
    cudaGetSymbolAddress((void**)&ATOM, g_ATOM);
    cudaGetSymbolAddress((void**)&ATOM2,g_ATOM2);

    const dim3 gE(1, (NEDGES + 127) / 128);
    const dim3 gEG(NB, (NEDGES + 127) / 128);
    const dim3 gA(1, (NATOMS + 127) / 128);

    cudaMemsetAsync(out, 0, NGRAPHS * sizeof(float));

    // ---- embedding block ----
    embed_fill_k<<<NEDGES, HD>>>(z, ei, ej, rbf, emb_table, emb_rbf_w, emb_rbf_b, G);
    gemm_k<<<gE, 256>>>(G, emb_w, emb_b, nullptr, nullptr, X, NEDGES, HD, 3 * HD, 1);

    // ---- out_block helper inlined via lambda ----
    auto out_block = [&](int k, const float* x) {
        cudaMemsetAsync(ATOM, 0, (size_t)NATOMS * HD * sizeof(float));
        edge_scatter_k<<<NEDGES, HD>>>(rbf, out_rbf_w + (size_t)k * NR * HD, x, ei, ATOM);
        gemm_k<<<gA, 256>>>(ATOM, out_lins_w + ((size_t)k * 3 + 0) * HD * HD,
                            out_lins_b + ((size_t)k * 3 + 0) * HD, nullptr, nullptr,
                            ATOM2, NATOMS, HD, HD, 1);
        gemm_k<<<gA, 256>>>(ATOM2, out_lins_w + ((size_t)k * 3 + 1) * HD * HD,
                            out_lins_b + ((size_t)k * 3 + 1) * HD, nullptr, nullptr,
                            ATOM, NATOMS, HD, HD, 1);
        gemm_k<<<gA, 256>>>(ATOM, out_lins_w + ((size_t)k * 3 + 2) * HD * HD,
                            out_lins_b + ((size_t)k * 3 + 2) * HD, nullptr, nullptr,
                            ATOM2, NATOMS, HD, HD, 1);
        dot_k<<<(NATOMS + 7) / 8, 256>>>(ATOM2, out_w + (size_t)k * HD, batch, out);
    };

    out_block(0, X);

    float* xa = X;
    float* xb = XS;
    for (int b = 0; b < NBLK; b++) {
        rbfp_k<<<NEDGES, HD>>>(rbf, int_rbf_w + (size_t)b * NR * HD, RBFP);
        sbfp_k<<<(NTRIP + 127) / 128, 128>>>(sbf, int_sbf_w + (size_t)b * NSNR * NB, SBFP);

        gemm_k<<<gE, 256>>>(xa, int_ji_w + (size_t)b * HD * HD, int_ji_b + (size_t)b * HD,
                            nullptr, nullptr, XJI, NEDGES, HD, HD, 1);
        gemm_k<<<gE, 256>>>(xa, int_kj_w + (size_t)b * HD * HD, int_kj_b + (size_t)b * HD,
                            nullptr, RBFP, XKJ, NEDGES, HD, HD, 1);

        wt_k<<<(HD * NB * HD) / 128, 128>>>(int_W + (size_t)b * HD * NB * HD, WT);
        gemm_k<<<gEG, 256>>>(XKJ, WT, nullptr, nullptr, nullptr, G, NEDGES, NB * HD, HD, 0);

        trip_k<<<(NTRIP + 7) / 8, 256>>>(G, SBFP, idx_kj, idx_ji, XJI);

        // residual before (1 layer)
        gemm_k<<<gE, 256>>>(XJI, int_bef_w + ((size_t)b * 2 + 0) * HD * HD,
                            int_bef_b + ((size_t)b * 2 + 0) * HD, nullptr, nullptr,
                            T1, NEDGES, HD, HD, 1);
        gemm_k<<<gE, 256>>>(T1, int_bef_w + ((size_t)b * 2 + 1) * HD * HD,
                            int_bef_b + ((size_t)b * 2 + 1) * HD, XJI, nullptr,
                            XJI, NEDGES, HD, HD, 1);

        // lin + skip
        gemm_k<<<gE, 256>>>(XJI, int_lin_w + (size_t)b * HD * HD, int_lin_b + (size_t)b * HD,
                            xa, nullptr, xb, NEDGES, HD, HD, 1);

        // residual after (2 layers)
        for (int r = 0; r < 2; r++) {
            gemm_k<<<gE, 256>>>(xb, int_aft_w + ((size_t)b * 4 + 2 * r + 0) * HD * HD,
                                int_aft_b + ((size_t)b * 4 + 2 * r + 0) * HD, nullptr, nullptr,
                                T1, NEDGES, HD, HD, 1);
            gemm_k<<<gE, 256>>>(T1, int_aft_w + ((size_t)b * 4 + 2 * r + 1) * HD * HD,
                                int_aft_b + ((size_t)b * 4 + 2 * r + 1) * HD, xb, nullptr,
                                xb, NEDGES, HD, HD, 1);
        }

        float* t = xa; xa = xb; xb = t;
        out_block(b + 1, xa);
    }
}

// round 3
// speedup vs baseline: 1.2797x; 1.2797x over previous
#include <cuda_runtime.h>
#include <math.h>

#define NATOMS 8000
#define NEDGES 100000
#define NTRIP  500000
#define NGRAPHS 64
#define HD 128
#define NR 6
#define NSNR 42
#define NB 8
#define NBLK 6

// ---------------- device scratch (no allocation allowed) ----------------
__device__ float g_X   [NEDGES*HD];
__device__ float g_XS  [NEDGES*HD];
__device__ float g_XJI [NEDGES*HD];
__device__ float g_XKJ [NEDGES*HD];
__device__ float g_T1  [NEDGES*HD];
__device__ float g_RBFP[NEDGES*HD];
__device__ float g_SBFP[(size_t)NTRIP*NBLK*NB];
__device__ float g_G   [(size_t)NEDGES*NB*HD];   // also reused as [E,384] embed input
__device__ float g_WT  [HD*NB*HD];
__device__ float g_ATOM [NATOMS*HD];
__device__ float g_ATOM2[NATOMS*HD];

__device__ __forceinline__ float silu(float x) { return x / (1.0f + expf(-x)); }

__device__ __forceinline__ unsigned f2tf32(float x) {
    unsigned r;
    asm("cvt.rna.tf32.f32 %0, %1;" : "=r"(r) : "f"(x));
    return r;
}

__device__ __forceinline__ void mma_tf32(float* c, const unsigned* a, const unsigned* b) {
    asm volatile(
        "mma.sync.aligned.m16n8k8.row.col.f32.tf32.tf32.f32 "
        "{%0,%1,%2,%3}, {%4,%5,%6,%7}, {%8,%9}, {%0,%1,%2,%3};"
        : "+f"(c[0]), "+f"(c[1]), "+f"(c[2]), "+f"(c[3])
        : "r"(a[0]), "r"(a[1]), "r"(a[2]), "r"(a[3]),
          "r"(b[0]), "r"(b[1]));
}

__device__ __forceinline__ void cp16(unsigned saddr, const float* g, int valid) {
    asm volatile("cp.async.cg.shared.global [%0], [%1], 16, %2;"
                 :: "r"(saddr), "l"(g), "r"(valid) : "memory");
}

// ---------------- tf32 tensor-core GEMM: C = epi(A[M,K] @ B[K,N] + bias) ----------------
// epi: (optional silu) -> (optional *mulv) -> (optional +addv). N,K multiples of 128/16.
#define AS_STRIDE 20
#define BS_STRIDE 136
__global__ __launch_bounds__(256, 2) void gemm_tf32(
    const float* __restrict__ A, const float* __restrict__ B,
    const float* __restrict__ bias, const float* __restrict__ addv,
    const float* __restrict__ mulv, float* __restrict__ C,
    int M, int N, int K, int act)
{
    __shared__ float As[2][128 * AS_STRIDE];
    __shared__ float Bs[2][16 * BS_STRIDE];

    const int tid = threadIdx.x;
    const int bM = blockIdx.y * 128;
    const int bN = blockIdx.x * 128;
    const int lane = tid & 31, warp = tid >> 5;
    const int gid = lane >> 2, tig = lane & 3;
    const int wm = warp >> 2, wn = warp & 3;     // 2 x 4 warp grid; warp tile 64x32

    float c[4][4][4];
#pragma unroll
    for (int i = 0; i < 4; i++)
#pragma unroll
        for (int j = 0; j < 4; j++)
#pragma unroll
            for (int q = 0; q < 4; q++) c[i][j][q] = 0.f;

    // global->smem mapping (2 float4 each for A and B)
    const int ar0 = tid >> 2, ak0 = (tid & 3) * 4;     // rows 0..63
    const int ar1 = ar0 + 64;
    const int br0 = tid >> 5, bc0 = (tid & 31) * 4;    // rows 0..7
    const int br1 = br0 + 8;

    unsigned sA = (unsigned)__cvta_generic_to_shared(&As[0][0]);
    unsigned sB = (unsigned)__cvta_generic_to_shared(&Bs[0][0]);
    const unsigned aBufB = 128 * AS_STRIDE * 4;
    const unsigned bBufB = 16 * BS_STRIDE * 4;

    auto issue = [&](int buf, int k0) {
        cp16(sA + buf * aBufB + (ar0 * AS_STRIDE + ak0) * 4,
             A + (size_t)(bM + ar0) * K + k0 + ak0, (bM + ar0) < M ? 16 : 0);
        cp16(sA + buf * aBufB + (ar1 * AS_STRIDE + ak0) * 4,
             A + (size_t)(bM + ar1) * K + k0 + ak0, (bM + ar1) < M ? 16 : 0);
        cp16(sB + buf * bBufB + (br0 * BS_STRIDE + bc0) * 4,
             B + (size_t)(k0 + br0) * N + bN + bc0, 16);
        cp16(sB + buf * bBufB + (br1 * BS_STRIDE + bc0) * 4,
             B + (size_t)(k0 + br1) * N + bN + bc0, 16);
        asm volatile("cp.async.commit_group;" ::: "memory");
    };

    const int nk = K >> 4;
    issue(0, 0);

    for (int kt = 0; kt < nk; kt++) {
        if (kt + 1 < nk) {
            issue((kt + 1) & 1, (kt + 1) * 16);
            asm volatile("cp.async.wait_group 1;" ::: "memory");
        } else {
            asm volatile("cp.async.wait_group 0;" ::: "memory");
        }
        __syncthreads();

        const float* as = As[kt & 1];
        const float* bs = Bs[kt & 1];
#pragma unroll
        for (int kk = 0; kk < 16; kk += 8) {
            unsigned af[4][4], bf[4][2];
#pragma unroll
            for (int fm = 0; fm < 4; fm++) {
                int m0 = wm * 64 + fm * 16;
                af[fm][0] = f2tf32(as[(m0 + gid) * AS_STRIDE + kk + tig]);
                af[fm][1] = f2tf32(as[(m0 + gid + 8) * AS_STRIDE + kk + tig]);
                af[fm][2] = f2tf32(as[(m0 + gid) * AS_STRIDE + kk + tig + 4]);
                af[fm][3] = f2tf32(as[(m0 + gid + 8) * AS_STRIDE + kk + tig + 4]);
            }
#pragma unroll
            for (int fn = 0; fn < 4; fn++) {
                int n0 = wn * 32 + fn * 8;
                bf[fn][0] = f2tf32(bs[(kk + tig) * BS_STRIDE + n0 + gid]);
                bf[fn][1] = f2tf32(bs[(kk + tig + 4) * BS_STRIDE + n0 + gid]);
            }
#pragma unroll
            for (int fm = 0; fm < 4; fm++)
#pragma unroll
                for (int fn = 0; fn < 4; fn++)
                    mma_tf32(c[fm][fn], af[fm], bf[fn]);
        }
        __syncthreads();
    }

    // epilogue
#pragma unroll
    for (int fm = 0; fm < 4; fm++) {
#pragma unroll
        for (int half = 0; half < 2; half++) {
            int row = bM + wm * 64 + fm * 16 + gid + half * 8;
            if (row >= M) continue;
#pragma unroll
            for (int fn = 0; fn < 4; fn++) {
                int col = bN + wn * 32 + fn * 8 + tig * 2;
                float v0 = c[fm][fn][half * 2 + 0] + (bias ? bias[col] : 0.f);
                float v1 = c[fm][fn][half * 2 + 1] + (bias ? bias[col + 1] : 0.f);
                if (act) { v0 = silu(v0); v1 = silu(v1); }
                size_t base = (size_t)row * N + col;
                if (mulv) {
                    float2 mv = *(const float2*)(mulv + base);
                    v0 *= mv.x; v1 *= mv.y;
                }
                if (addv) {
                    float2 av = *(const float2*)(addv + base);
                    v0 += av.x; v1 += av.y;
                }
                *(float2*)(C + base) = make_float2(v0, v1);
            }
        }
    }
}

// ---------------- embedding: build A_emb[E,384] = [h_i | h_j | silu(rbf@W+b)] ----------------
__global__ void embed_fill_k(const int* __restrict__ z, const int* __restrict__ ei,
                             const int* __restrict__ ej, const float* __restrict__ rbf,
                             const float* __restrict__ emb_table,
                             const float* __restrict__ erw, const float* __restrict__ erb,
                             float* __restrict__ Aemb)
{
    int e = blockIdx.x, h = threadIdx.x;
    int zi = z[ei[e]], zj = z[ej[e]];
    float s = erb[h];
    const float* rr = rbf + (size_t)e * NR;
#pragma unroll
    for (int r = 0; r < NR; r++) s += rr[r] * erw[r * HD + h];
    size_t base = (size_t)e * (3 * HD);
    Aemb[base + h]           = emb_table[(size_t)zi * HD + h];
    Aemb[base + HD + h]      = emb_table[(size_t)zj * HD + h];
    Aemb[base + 2 * HD + h]  = silu(s);
}

// ---------------- rbf projection: RBFP[e,h] = rbf[e,:] @ W[:,h] ----------------
__global__ void rbfp_k(const float* __restrict__ rbf, const float* __restrict__ w,
                       float* __restrict__ outp)
{
    int e = blockIdx.x, h = threadIdx.x;
    const float* rr = rbf + (size_t)e * NR;
    float s = 0.f;
#pragma unroll
    for (int r = 0; r < NR; r++) s += rr[r] * w[r * HD + h];
    outp[(size_t)e * HD + h] = s;
}

// ---------------- sbf projection, ALL blocks: SBFP[t, b*8+j] ----------------
__global__ void sbfp_all_k(const float* __restrict__ sbf, const float* __restrict__ w,
                           float* __restrict__ outp)
{
    __shared__ float ws[NBLK * NSNR * NB];   // 2016 floats
    for (int idx = threadIdx.x; idx < NBLK * NSNR * NB; idx += blockDim.x) ws[idx] = w[idx];
    __syncthreads();
    int t = blockIdx.x * blockDim.x + threadIdx.x;
    if (t >= NTRIP) return;
    float sr[NSNR];
    const float* s = sbf + (size_t)t * NSNR;
#pragma unroll
    for (int r = 0; r < NSNR; r++) sr[r] = s[r];
    float* op = outp + (size_t)t * (NBLK * NB);
#pragma unroll
    for (int b = 0; b < NBLK; b++) {
        float acc[NB];
#pragma unroll
        for (int j = 0; j < NB; j++) acc[j] = 0.f;
        for (int r = 0; r < NSNR; r++) {
            float sv = sr[r];
#pragma unroll
            for (int j = 0; j < NB; j++) acc[j] += sv * ws[b * NSNR * NB + r * NB + j];
        }
#pragma unroll
        for (int j = 0; j < NB; j++) op[b * NB + j] = acc[j];
    }
}

// ---------------- W transpose: WT[l*1024 + j*128 + i] = W[i*1024 + j*128 + l] ----------------
__global__ void wt_k(const float* __restrict__ W, float* __restrict__ WT)
{
    int idx = blockIdx.x * blockDim.x + threadIdx.x;   // 131072 elems
    int l = idx >> 10;
    int rest = idx & 1023;
    int j = rest >> 7;
    int i = rest & 127;
    WT[idx] = W[(size_t)i * (NB * HD) + j * HD + l];
}

// ---------------- triplet scatter: M[idx_ji[w],:] += sum_j sbf_p[w,j] * G[idx_kj[w], j, :] ----
__global__ __launch_bounds__(256) void trip_k(
    const float* __restrict__ G, const float* __restrict__ sbfp,
    const int* __restrict__ idx_kj, const int* __restrict__ idx_ji,
    float* __restrict__ Mo)
{
    int w = blockIdx.x * (blockDim.x >> 5) + (threadIdx.x >> 5);
    if (w >= NTRIP) return;
    int lane = threadIdx.x & 31;
    int kj = idx_kj[w], ji = idx_ji[w];
    float sv = (lane < NB) ? sbfp[(size_t)w * (NBLK * NB) + lane] : 0.f;
    const float* gr = G + (size_t)kj * (NB * HD) + lane * 4;
    float4 acc = make_float4(0.f, 0.f, 0.f, 0.f);
#pragma unroll
    for (int j = 0; j < NB; j++) {
        float s = __shfl_sync(0xffffffffu, sv, j);
        float4 g = *(const float4*)(gr + j * HD);
        acc.x += s * g.x; acc.y += s * g.y; acc.z += s * g.z; acc.w += s * g.w;
    }
    float* mo = Mo + (size_t)ji * HD + lane * 4;
    atomicAdd(mo + 0, acc.x);
    atomicAdd(mo + 1, acc.y);
    atomicAdd(mo + 2, acc.z);
    atomicAdd(mo + 3, acc.w);
}

// ---------------- out-block edge scatter: ATOM[i[e],h] += (rbf@orw)[h] * x[e,h] ------------
__global__ void edge_scatter_k(const float* __restrict__ rbf, const float* __restrict__ orw,
                               const float* __restrict__ x, const int* __restrict__ ei,
                               float* __restrict__ atom)
{
    int e = blockIdx.x, h = threadIdx.x;
    const float* rr = rbf + (size_t)e * NR;
    float rp = 0.f;
#pragma unroll
    for (int r = 0; r < NR; r++) rp += rr[r] * orw[r * HD + h];
    float v = rp * x[(size_t)e * HD + h];
    atomicAdd(&atom[(size_t)ei[e] * HD + h], v);
}

// ---------------- final per-atom dot + graph segment sum ----------------
__global__ void dot_k(const float* __restrict__ atom2, const float* __restrict__ ow,
                      const int* __restrict__ batch, float* __restrict__ out)
{
    int a = blockIdx.x * (blockDim.x >> 5) + (threadIdx.x >> 5);
    if (a >= NATOMS) return;
    int lane = threadIdx.x & 31;
    const float* ar = atom2 + (size_t)a * HD + lane * 4;
    const float* wr = ow + lane * 4;
    float s = ar[0] * wr[0] + ar[1] * wr[1] + ar[2] * wr[2] + ar[3] * wr[3];
#pragma unroll
    for (int o = 16; o > 0; o >>= 1) s += __shfl_down_sync(0xffffffffu, s, o);
    if (lane == 0) atomicAdd(&out[batch[a]], s);
}

// ==========================================================================================
extern "C" void kernel_launch(void* const* d_in, const int* in_sizes, int n_in,
                              void* d_out, int out_size)
{
    const int*   z        = (const int*)  d_in[0];
    const float* rbf      = (const float*)d_in[1];
    const float* sbf      = (const float*)d_in[2];
    const int*   ei       = (const int*)  d_in[3];
    const int*   ej       = (const int*)  d_in[4];
    const int*   idx_kj   = (const int*)  d_in[5];
    const int*   idx_ji   = (const int*)  d_in[6];
    const int*   batch    = (const int*)  d_in[7];
    const float* emb_table= (const float*)d_in[8];
    const float* emb_rbf_w= (const float*)d_in[9];
    const float* emb_rbf_b= (const float*)d_in[10];
    const float* emb_w    = (const float*)d_in[11];
    const float* emb_b    = (const float*)d_in[12];
    const float* int_rbf_w= (const float*)d_in[13];
    const float* int_sbf_w= (const float*)d_in[14];
    const float* int_kj_w = (const float*)d_in[15];
    const float* int_kj_b = (const float*)d_in[16];
    const float* int_ji_w = (const float*)d_in[17];
    const float* int_ji_b = (const float*)d_in[18];
    const float* int_W    = (const float*)d_in[19];
    const float* int_bef_w= (const float*)d_in[20];
    const float* int_bef_b= (const float*)d_in[21];
    const float* int_lin_w= (const float*)d_in[22];
    const float* int_lin_b= (const float*)d_in[23];
    const float* int_aft_w= (const float*)d_in[24];
    const float* int_aft_b= (const float*)d_in[25];
    const float* out_rbf_w= (const float*)d_in[26];
    const float* out_lins_w=(const float*)d_in[27];
    const float* out_lins_b=(const float*)d_in[28];
    const float* out_w    = (const float*)d_in[29];
    float* out = (float*)d_out;

    float *X, *XS, *XJI, *XKJ, *T1, *RBFP, *SBFP, *G, *WT, *ATOM, *ATOM2;
    cudaGetSymbolAddress((void**)&X,    g_X);
    cudaGetSymbolAddress((void**)&XS,   g_XS);
    cudaGetSymbolAddress((void**)&XJI,  g_XJI);
    cudaGetSymbolAddress((void**)&XKJ,  g_XKJ);
    cudaGetSymbolAddress((void**)&T1,   g_T1);
    cudaGetSymbolAddress((void**)&RBFP, g_RBFP);
    cudaGetSymbolAddress((void**)&SBFP, g_SBFP);
    cudaGetSymbolAddress((void**)&G,    g_G);
    cudaGetSymbolAddress((void**)&WT,   g_WT);
    cudaGetSymbolAddress((void**)&ATOM, g_ATOM);
    cudaGetSymbolAddress((void**)&ATOM2,g_ATOM2);

    const dim3 gE(1, (NEDGES + 127) / 128);
    const dim3 gEG(NB, (NEDGES + 127) / 128);
    const dim3 gA(1, (NATOMS + 127) / 128);

    cudaMemsetAsync(out, 0, NGRAPHS * sizeof(float));

    // all sbf projections up front (read sbf once)
    sbfp_all_k<<<(NTRIP + 127) / 128, 128>>>(sbf, int_sbf_w, SBFP);

    // ---- embedding block ----
    embed_fill_k<<<NEDGES, HD>>>(z, ei, ej, rbf, emb_table, emb_rbf_w, emb_rbf_b, G);
    gemm_tf32<<<gE, 256>>>(G, emb_w, emb_b, nullptr, nullptr, X, NEDGES, HD, 3 * HD, 1);

    auto out_block = [&](int k, const float* x) {
        cudaMemsetAsync(ATOM, 0, (size_t)NATOMS * HD * sizeof(float));
        edge_scatter_k<<<NEDGES, HD>>>(rbf, out_rbf_w + (size_t)k * NR * HD, x, ei, ATOM);
        gemm_tf32<<<gA, 256>>>(ATOM, out_lins_w + ((size_t)k * 3 + 0) * HD * HD,
                               out_lins_b + ((size_t)k * 3 + 0) * HD, nullptr, nullptr,
                               ATOM2, NATOMS, HD, HD, 1);
        gemm_tf32<<<gA, 256>>>(ATOM2, out_lins_w + ((size_t)k * 3 + 1) * HD * HD,
                               out_lins_b + ((size_t)k * 3 + 1) * HD, nullptr, nullptr,
                               ATOM, NATOMS, HD, HD, 1);
        gemm_tf32<<<gA, 256>>>(ATOM, out_lins_w + ((size_t)k * 3 + 2) * HD * HD,
                               out_lins_b + ((size_t)k * 3 + 2) * HD, nullptr, nullptr,
                               ATOM2, NATOMS, HD, HD, 1);
        dot_k<<<(NATOMS + 7) / 8, 256>>>(ATOM2, out_w + (size_t)k * HD, batch, out);
    };

    out_block(0, X);

    float* xa = X;
    float* xb = XS;
    for (int b = 0; b < NBLK; b++) {
        rbfp_k<<<NEDGES, HD>>>(rbf, int_rbf_w + (size_t)b * NR * HD, RBFP);

        gemm_tf32<<<gE, 256>>>(xa, int_ji_w + (size_t)b * HD * HD, int_ji_b + (size_t)b * HD,
                               nullptr, nullptr, XJI, NEDGES, HD, HD, 1);
        gemm_tf32<<<gE, 256>>>(xa, int_kj_w + (size_t)b * HD * HD, int_kj_b + (size_t)b * HD,
                               nullptr, RBFP, XKJ, NEDGES, HD, HD, 1);

        wt_k<<<(HD * NB * HD) / 128, 128>>>(int_W + (size_t)b * HD * NB * HD, WT);
        gemm_tf32<<<gEG, 256>>>(XKJ, WT, nullptr, nullptr, nullptr, G, NEDGES, NB * HD, HD, 0);

        trip_k<<<(NTRIP + 7) / 8, 256>>>(G, SBFP + (size_t)b * NB, idx_kj, idx_ji, XJI);

        // residual before (1 layer)
        gemm_tf32<<<gE, 256>>>(XJI, int_bef_w + ((size_t)b * 2 + 0) * HD * HD,
                               int_bef_b + ((size_t)b * 2 + 0) * HD, nullptr, nullptr,
                               T1, NEDGES, HD, HD, 1);
        gemm_tf32<<<gE, 256>>>(T1, int_bef_w + ((size_t)b * 2 + 1) * HD * HD,
                               int_bef_b + ((size_t)b * 2 + 1) * HD, XJI, nullptr,
                               XJI, NEDGES, HD, HD, 1);

        // lin + skip
        gemm_tf32<<<gE, 256>>>(XJI, int_lin_w + (size_t)b * HD * HD, int_lin_b + (size_t)b * HD,
                               xa, nullptr, xb, NEDGES, HD, HD, 1);

        // residual after (2 layers)
        for (int r = 0; r < 2; r++) {
            gemm_tf32<<<gE, 256>>>(xb, int_aft_w + ((size_t)b * 4 + 2 * r + 0) * HD * HD,
                                   int_aft_b + ((size_t)b * 4 + 2 * r + 0) * HD, nullptr, nullptr,
                                   T1, NEDGES, HD, HD, 1);
            gemm_tf32<<<gE, 256>>>(T1, int_aft_w + ((size_t)b * 4 + 2 * r + 1) * HD * HD,
                                   int_aft_b + ((size_t)b * 4 + 2 * r + 1) * HD, xb, nullptr,
                                   xb, NEDGES, HD, HD, 1);
        }

        float* t = xa; xa = xb; xb = t;
        out_block(b + 1, xa);
    }
}

// round 4
// speedup vs baseline: 1.9400x; 1.5160x over previous
#include <cuda_runtime.h>
#include <cuda_bf16.h>
#include <math.h>

#define NATOMS 8000
#define NEDGES 100000
#define NTRIP  500000
#define NGRAPHS 64
#define HD 128
#define NR 6
#define NSNR 42
#define NB 8
#define NBLK 6

// ---------------- device scratch (no allocation allowed) ----------------
__device__ float g_XSAVE[(size_t)(NBLK + 1) * NEDGES * HD];   // x snapshot per block
__device__ float g_XJI [NEDGES*HD];
__device__ float g_XKJ [NEDGES*HD];
__device__ float g_T1  [NEDGES*HD];
__device__ float g_RBFP[NEDGES*HD];
__device__ float g_SBFP[(size_t)NTRIP*NBLK*NB];
__device__ float g_AEMB[(size_t)NEDGES*3*HD];                  // embed input [E,384]
__device__ __nv_bfloat16 g_Gh[(size_t)NEDGES*NB*HD];           // G in bf16
__device__ float g_WT  [HD*NB*HD];
__device__ float g_ATOM7 [(size_t)7*NATOMS*HD];
__device__ float g_ATOM7B[(size_t)7*NATOMS*HD];

__device__ __forceinline__ float silu(float x) { return x / (1.0f + expf(-x)); }

__device__ __forceinline__ unsigned f2tf32(float x) {
    unsigned r;
    asm("cvt.rna.tf32.f32 %0, %1;" : "=r"(r) : "f"(x));
    return r;
}

__device__ __forceinline__ void mma_tf32(float* c, const unsigned* a, const unsigned* b) {
    asm volatile(
        "mma.sync.aligned.m16n8k8.row.col.f32.tf32.tf32.f32 "
        "{%0,%1,%2,%3}, {%4,%5,%6,%7}, {%8,%9}, {%0,%1,%2,%3};"
        : "+f"(c[0]), "+f"(c[1]), "+f"(c[2]), "+f"(c[3])
        : "r"(a[0]), "r"(a[1]), "r"(a[2]), "r"(a[3]),
          "r"(b[0]), "r"(b[1]));
}

__device__ __forceinline__ void cp16(unsigned saddr, const float* g, int valid) {
    asm volatile("cp.async.cg.shared.global [%0], [%1], 16, %2;"
                 :: "r"(saddr), "l"(g), "r"(valid) : "memory");
}

// ---------------- tf32 tensor-core GEMM: C = epi(A[M,K] @ B[K,N] + bias) ----------------
// epi: (optional silu) -> (optional *mulv) -> (optional +addv); optional bf16 output.
// Batched over blockIdx.z with element strides aZ/bZ/biasZ/cZ.
#define AS_STRIDE 20
#define BS_STRIDE 136
__global__ __launch_bounds__(256, 2) void gemm_tf32(
    const float* __restrict__ A, const float* __restrict__ B,
    const float* __restrict__ bias, const float* __restrict__ addv,
    const float* __restrict__ mulv, void* __restrict__ Cv,
    int M, int N, int K, int act, int outBf16,
    size_t aZ, size_t bZ, size_t biasZ, size_t cZ)
{
    __shared__ float As[2][128 * AS_STRIDE];
    __shared__ float Bs[2][16 * BS_STRIDE];

    A += blockIdx.z * aZ;
    B += blockIdx.z * bZ;
    if (bias) bias += blockIdx.z * biasZ;

    const int tid = threadIdx.x;
    const int bM = blockIdx.y * 128;
    const int bN = blockIdx.x * 128;
    const int lane = tid & 31, warp = tid >> 5;
    const int gid = lane >> 2, tig = lane & 3;
    const int wm = warp >> 2, wn = warp & 3;     // 2 x 4 warp grid; warp tile 64x32

    float c[4][4][4];
#pragma unroll
    for (int i = 0; i < 4; i++)
#pragma unroll
        for (int j = 0; j < 4; j++)
#pragma unroll
            for (int q = 0; q < 4; q++) c[i][j][q] = 0.f;

    const int ar0 = tid >> 2, ak0 = (tid & 3) * 4;     // rows 0..63
    const int ar1 = ar0 + 64;
    const int br0 = tid >> 5, bc0 = (tid & 31) * 4;    // rows 0..7
    const int br1 = br0 + 8;

    unsigned sA = (unsigned)__cvta_generic_to_shared(&As[0][0]);
    unsigned sB = (unsigned)__cvta_generic_to_shared(&Bs[0][0]);
    const unsigned aBufB = 128 * AS_STRIDE * 4;
    const unsigned bBufB = 16 * BS_STRIDE * 4;

    auto issue = [&](int buf, int k0) {
        cp16(sA + buf * aBufB + (ar0 * AS_STRIDE + ak0) * 4,
             A + (size_t)(bM + ar0) * K + k0 + ak0, (bM + ar0) < M ? 16 : 0);
        cp16(sA + buf * aBufB + (ar1 * AS_STRIDE + ak0) * 4,
             A + (size_t)(bM + ar1) * K + k0 + ak0, (bM + ar1) < M ? 16 : 0);
        cp16(sB + buf * bBufB + (br0 * BS_STRIDE + bc0) * 4,
             B + (size_t)(k0 + br0) * N + bN + bc0, 16);
        cp16(sB + buf * bBufB + (br1 * BS_STRIDE + bc0) * 4,
             B + (size_t)(k0 + br1) * N + bN + bc0, 16);
        asm volatile("cp.async.commit_group;" ::: "memory");
    };

    const int nk = K >> 4;
    issue(0, 0);

    for (int kt = 0; kt < nk; kt++) {
        if (kt + 1 < nk) {
            issue((kt + 1) & 1, (kt + 1) * 16);
            asm volatile("cp.async.wait_group 1;" ::: "memory");
        } else {
            asm volatile("cp.async.wait_group 0;" ::: "memory");
        }
        __syncthreads();

        const float* as = As[kt & 1];
        const float* bs = Bs[kt & 1];
#pragma unroll
        for (int kk = 0; kk < 16; kk += 8) {
            unsigned af[4][4], bf[4][2];
#pragma unroll
            for (int fm = 0; fm < 4; fm++) {
                int m0 = wm * 64 + fm * 16;
                af[fm][0] = f2tf32(as[(m0 + gid) * AS_STRIDE + kk + tig]);
                af[fm][1] = f2tf32(as[(m0 + gid + 8) * AS_STRIDE + kk + tig]);
                af[fm][2] = f2tf32(as[(m0 + gid) * AS_STRIDE + kk + tig + 4]);
                af[fm][3] = f2tf32(as[(m0 + gid + 8) * AS_STRIDE + kk + tig + 4]);
            }
#pragma unroll
            for (int fn = 0; fn < 4; fn++) {
                int n0 = wn * 32 + fn * 8;
                bf[fn][0] = f2tf32(bs[(kk + tig) * BS_STRIDE + n0 + gid]);
                bf[fn][1] = f2tf32(bs[(kk + tig + 4) * BS_STRIDE + n0 + gid]);
            }
#pragma unroll
            for (int fm = 0; fm < 4; fm++)
#pragma unroll
                for (int fn = 0; fn < 4; fn++)
                    mma_tf32(c[fm][fn], af[fm], bf[fn]);
        }
        __syncthreads();
    }

    // epilogue
    float* Cf = (float*)Cv + blockIdx.z * cZ;
    __nv_bfloat16* Ch = (__nv_bfloat16*)Cv + blockIdx.z * cZ;

#pragma unroll
    for (int fm = 0; fm < 4; fm++) {
#pragma unroll
        for (int half = 0; half < 2; half++) {
            int row = bM + wm * 64 + fm * 16 + gid + half * 8;
            if (row >= M) continue;
#pragma unroll
            for (int fn = 0; fn < 4; fn++) {
                int col = bN + wn * 32 + fn * 8 + tig * 2;
                float v0 = c[fm][fn][half * 2 + 0] + (bias ? bias[col] : 0.f);
                float v1 = c[fm][fn][half * 2 + 1] + (bias ? bias[col + 1] : 0.f);
                if (act) { v0 = silu(v0); v1 = silu(v1); }
                size_t base = (size_t)row * N + col;
                if (mulv) {
                    float2 mv = *(const float2*)(mulv + base);
                    v0 *= mv.x; v1 *= mv.y;
                }
                if (addv) {
                    float2 av = *(const float2*)(addv + base);
                    v0 += av.x; v1 += av.y;
                }
                if (outBf16) {
                    *(__nv_bfloat162*)(Ch + base) =
                        __float22bfloat162_rn(make_float2(v0, v1));
                } else {
                    *(float2*)(Cf + base) = make_float2(v0, v1);
                }
            }
        }
    }
}

// ---------------- embedding: build A_emb[E,384] = [h_i | h_j | silu(rbf@W+b)] ----------------
__global__ void embed_fill_k(const int* __restrict__ z, const int* __restrict__ ei,
                             const int* __restrict__ ej, const float* __restrict__ rbf,
                             const float* __restrict__ emb_table,
                             const float* __restrict__ erw, const float* __restrict__ erb,
                             float* __restrict__ Aemb)
{
    int e = blockIdx.x, h = threadIdx.x;
    int zi = z[ei[e]], zj = z[ej[e]];
    float s = erb[h];
    const float* rr = rbf + (size_t)e * NR;
#pragma unroll
    for (int r = 0; r < NR; r++) s += rr[r] * erw[r * HD + h];
    size_t base = (size_t)e * (3 * HD);
    Aemb[base + h]           = emb_table[(size_t)zi * HD + h];
    Aemb[base + HD + h]      = emb_table[(size_t)zj * HD + h];
    Aemb[base + 2 * HD + h]  = silu(s);
}

// ---------------- rbf projection: RBFP[e,h] = rbf[e,:] @ W[:,h] ----------------
__global__ void rbfp_k(const float* __restrict__ rbf, const float* __restrict__ w,
                       float* __restrict__ outp)
{
    int e = blockIdx.x, h = threadIdx.x;
    const float* rr = rbf + (size_t)e * NR;
    float s = 0.f;
#pragma unroll
    for (int r = 0; r < NR; r++) s += rr[r] * w[r * HD + h];
    outp[(size_t)e * HD + h] = s;
}

// ---------------- sbf projection, ALL blocks: SBFP[t, b*8+j] ----------------
__global__ void sbfp_all_k(const float* __restrict__ sbf, const float* __restrict__ w,
                           float* __restrict__ outp)
{
    __shared__ float ws[NBLK * NSNR * NB];   // 2016 floats
    for (int idx = threadIdx.x; idx < NBLK * NSNR * NB; idx += blockDim.x) ws[idx] = w[idx];
    __syncthreads();
    int t = blockIdx.x * blockDim.x + threadIdx.x;
    if (t >= NTRIP) return;
    float sr[NSNR];
    const float* s = sbf + (size_t)t * NSNR;
#pragma unroll
    for (int r = 0; r < NSNR; r++) sr[r] = s[r];
    float* op = outp + (size_t)t * (NBLK * NB);
#pragma unroll
    for (int b = 0; b < NBLK; b++) {
        float acc[NB];
#pragma unroll
        for (int j = 0; j < NB; j++) acc[j] = 0.f;
        for (int r = 0; r < NSNR; r++) {
            float sv = sr[r];
#pragma unroll
            for (int j = 0; j < NB; j++) acc[j] += sv * ws[b * NSNR * NB + r * NB + j];
        }
#pragma unroll
        for (int j = 0; j < NB; j++) op[b * NB + j] = acc[j];
    }
}

// ---------------- W transpose: WT[l*1024 + j*128 + i] = W[i*1024 + j*128 + l] ----------------
__global__ void wt_k(const float* __restrict__ W, float* __restrict__ WT)
{
    int idx = blockIdx.x * blockDim.x + threadIdx.x;   // 131072 elems
    int l = idx >> 10;
    int rest = idx & 1023;
    int j = rest >> 7;
    int i = rest & 127;
    WT[idx] = W[(size_t)i * (NB * HD) + j * HD + l];
}

// ---------------- triplet scatter: M[idx_ji[w],:] += sum_j sbf_p[w,j] * Gh[idx_kj[w], j, :] --
__global__ __launch_bounds__(256) void trip_k(
    const __nv_bfloat16* __restrict__ Gh, const float* __restrict__ sbfp,
    const int* __restrict__ idx_kj, const int* __restrict__ idx_ji,
    float* __restrict__ Mo)
{
    int w = blockIdx.x * (blockDim.x >> 5) + (threadIdx.x >> 5);
    if (w >= NTRIP) return;
    int lane = threadIdx.x & 31;
    int kj = idx_kj[w], ji = idx_ji[w];
    float sv = (lane < NB) ? sbfp[(size_t)w * (NBLK * NB) + lane] : 0.f;
    const __nv_bfloat16* gr = Gh + (size_t)kj * (NB * HD) + lane * 4;
    float4 acc = make_float4(0.f, 0.f, 0.f, 0.f);
#pragma unroll
    for (int j = 0; j < NB; j++) {
        float s = __shfl_sync(0xffffffffu, sv, j);
        uint2 u = *(const uint2*)(gr + j * HD);
        __nv_bfloat162 p0 = *reinterpret_cast<__nv_bfloat162*>(&u.x);
        __nv_bfloat162 p1 = *reinterpret_cast<__nv_bfloat162*>(&u.y);
        float2 f0 = __bfloat1622float2(p0);
        float2 f1 = __bfloat1622float2(p1);
        acc.x += s * f0.x; acc.y += s * f0.y; acc.z += s * f1.x; acc.w += s * f1.y;
    }
    float* mo = Mo + (size_t)ji * HD + lane * 4;
    atomicAdd(mo + 0, acc.x);
    atomicAdd(mo + 1, acc.y);
    atomicAdd(mo + 2, acc.z);
    atomicAdd(mo + 3, acc.w);
}

// ---------------- batched out-block edge scatter over k=0..6 -----------------
// ATOM7[k, i[e], h] += (rbf@orw_k)[h] * xsave[k, e, h]
__global__ void edge_scatter7_k(const float* __restrict__ rbf, const float* __restrict__ orw,
                                const float* __restrict__ xsave, const int* __restrict__ ei,
                                float* __restrict__ atom)
{
    int e = blockIdx.x, k = blockIdx.y, h = threadIdx.x;
    const float* rr = rbf + (size_t)e * NR;
    const float* w = orw + (size_t)k * NR * HD;
    float rp = 0.f;
#pragma unroll
    for (int r = 0; r < NR; r++) rp += rr[r] * w[r * HD + h];
    float v = rp * xsave[(size_t)k * NEDGES * HD + (size_t)e * HD + h];
    atomicAdd(&atom[(size_t)k * NATOMS * HD + (size_t)ei[e] * HD + h], v);
}

// ---------------- batched final per-atom dot + graph segment sum ----------------
__global__ void dot7_k(const float* __restrict__ atom2, const float* __restrict__ ow,
                       const int* __restrict__ batch, float* __restrict__ out)
{
    int a = blockIdx.x * (blockDim.x >> 5) + (threadIdx.x >> 5);
    if (a >= NATOMS) return;
    int k = blockIdx.y;
    int lane = threadIdx.x & 31;
    const float* ar = atom2 + (size_t)k * NATOMS * HD + (size_t)a * HD + lane * 4;
    const float* wr = ow + (size_t)k * HD + lane * 4;
    float s = ar[0] * wr[0] + ar[1] * wr[1] + ar[2] * wr[2] + ar[3] * wr[3];
#pragma unroll
    for (int o = 16; o > 0; o >>= 1) s += __shfl_down_sync(0xffffffffu, s, o);
    if (lane == 0) atomicAdd(&out[batch[a]], s);
}

// ==========================================================================================
extern "C" void kernel_launch(void* const* d_in, const int* in_sizes, int n_in,
                              void* d_out, int out_size)
{
    const int*   z        = (const int*)  d_in[0];
    const float* rbf      = (const float*)d_in[1];
    const float* sbf      = (const float*)d_in[2];
    const int*   ei       = (const int*)  d_in[3];
    const int*   ej       = (const int*)  d_in[4];
    const int*   idx_kj   = (const int*)  d_in[5];
    const int*   idx_ji   = (const int*)  d_in[6];
    const int*   batch    = (const int*)  d_in[7];
    const float* emb_table= (const float*)d_in[8];
    const float* emb_rbf_w= (const float*)d_in[9];
    const float* emb_rbf_b= (const float*)d_in[10];
    const float* emb_w    = (const float*)d_in[11];
    const float* emb_b    = (const float*)d_in[12];
    const float* int_rbf_w= (const float*)d_in[13];
    const float* int_sbf_w= (const float*)d_in[14];
    const float* int_kj_w = (const float*)d_in[15];
    const float* int_kj_b = (const float*)d_in[16];
    const float* int_ji_w = (const float*)d_in[17];
    const float* int_ji_b = (const float*)d_in[18];
    const float* int_W    = (const float*)d_in[19];
    const float* int_bef_w= (const float*)d_in[20];
    const float* int_bef_b= (const float*)d_in[21];
    const float* int_lin_w= (const float*)d_in[22];
    const float* int_lin_b= (const float*)d_in[23];
    const float* int_aft_w= (const float*)d_in[24];
    const float* int_aft_b= (const float*)d_in[25];
    const float* out_rbf_w= (const float*)d_in[26];
    const float* out_lins_w=(const float*)d_in[27];
    const float* out_lins_b=(const float*)d_in[28];
    const float* out_w    = (const float*)d_in[29];
    float* out = (float*)d_out;

    float *XSAVE, *XJI, *XKJ, *T1, *RBFP, *SBFP, *AEMB, *WT, *ATOM7, *ATOM7B;
    __nv_bfloat16* Gh;
    cudaGetSymbolAddress((void**)&XSAVE, g_XSAVE);
    cudaGetSymbolAddress((void**)&XJI,  g_XJI);
    cudaGetSymbolAddress((void**)&XKJ,  g_XKJ);
    cudaGetSymbolAddress((void**)&T1,   g_T1);
    cudaGetSymbolAddress((void**)&RBFP, g_RBFP);
    cudaGetSymbolAddress((void**)&SBFP, g_SBFP);
    cudaGetSymbolAddress((void**)&AEMB, g_AEMB);
    cudaGetSymbolAddress((void**)&Gh,   g_Gh);
    cudaGetSymbolAddress((void**)&WT,   g_WT);
    cudaGetSymbolAddress((void**)&ATOM7, g_ATOM7);
    cudaGetSymbolAddress((void**)&ATOM7B,g_ATOM7B);

    const dim3 gE(1, (NEDGES + 127) / 128);
    const dim3 gEG(NB, (NEDGES + 127) / 128);
    const dim3 gA7(1, (NATOMS + 127) / 128, 7);

    const size_t EH = (size_t)NEDGES * HD;

    cudaMemsetAsync(out, 0, NGRAPHS * sizeof(float));
    cudaMemsetAsync(ATOM7, 0, (size_t)7 * NATOMS * HD * sizeof(float));

    // all sbf projections up front (read sbf once)
    sbfp_all_k<<<(NTRIP + 127) / 128, 128>>>(sbf, int_sbf_w, SBFP);

    // ---- embedding block -> XSAVE[0] ----
    embed_fill_k<<<NEDGES, HD>>>(z, ei, ej, rbf, emb_table, emb_rbf_w, emb_rbf_b, AEMB);
    gemm_tf32<<<gE, 256>>>(AEMB, emb_w, emb_b, nullptr, nullptr, XSAVE,
                           NEDGES, HD, 3 * HD, 1, 0, 0, 0, 0, 0);

    for (int b = 0; b < NBLK; b++) {
        float* xa = XSAVE + (size_t)b * EH;
        float* xb = XSAVE + (size_t)(b + 1) * EH;

        rbfp_k<<<NEDGES, HD>>>(rbf, int_rbf_w + (size_t)b * NR * HD, RBFP);

        gemm_tf32<<<gE, 256>>>(xa, int_ji_w + (size_t)b * HD * HD, int_ji_b + (size_t)b * HD,
                               nullptr, nullptr, XJI, NEDGES, HD, HD, 1, 0, 0, 0, 0, 0);
        gemm_tf32<<<gE, 256>>>(xa, int_kj_w + (size_t)b * HD * HD, int_kj_b + (size_t)b * HD,
                               nullptr, RBFP, XKJ, NEDGES, HD, HD, 1, 0, 0, 0, 0, 0);

        wt_k<<<(HD * NB * HD) / 128, 128>>>(int_W + (size_t)b * HD * NB * HD, WT);
        gemm_tf32<<<gEG, 256>>>(XKJ, WT, nullptr, nullptr, nullptr, Gh,
                                NEDGES, NB * HD, HD, 0, 1, 0, 0, 0, 0);

        trip_k<<<(NTRIP + 7) / 8, 256>>>(Gh, SBFP + (size_t)b * NB, idx_kj, idx_ji, XJI);

        // residual before (1 layer)
        gemm_tf32<<<gE, 256>>>(XJI, int_bef_w + ((size_t)b * 2 + 0) * HD * HD,
                               int_bef_b + ((size_t)b * 2 + 0) * HD, nullptr, nullptr,
                               T1, NEDGES, HD, HD, 1, 0, 0, 0, 0, 0);
        gemm_tf32<<<gE, 256>>>(T1, int_bef_w + ((size_t)b * 2 + 1) * HD * HD,
                               int_bef_b + ((size_t)b * 2 + 1) * HD, XJI, nullptr,
                               XJI, NEDGES, HD, HD, 1, 0, 0, 0, 0, 0);

        // lin + skip -> xb
        gemm_tf32<<<gE, 256>>>(XJI, int_lin_w + (size_t)b * HD * HD, int_lin_b + (size_t)b * HD,
                               xa, nullptr, xb, NEDGES, HD, HD, 1, 0, 0, 0, 0, 0);

        // residual after (2 layers), in place on xb
        for (int r = 0; r < 2; r++) {
            gemm_tf32<<<gE, 256>>>(xb, int_aft_w + ((size_t)b * 4 + 2 * r + 0) * HD * HD,
                                   int_aft_b + ((size_t)b * 4 + 2 * r + 0) * HD, nullptr, nullptr,
                                   T1, NEDGES, HD, HD, 1, 0, 0, 0, 0, 0);
            gemm_tf32<<<gE, 256>>>(T1, int_aft_w + ((size_t)b * 4 + 2 * r + 1) * HD * HD,
                                   int_aft_b + ((size_t)b * 4 + 2 * r + 1) * HD, xb, nullptr,
                                   xb, NEDGES, HD, HD, 1, 0, 0, 0, 0, 0);
        }
    }

    // ---- all 7 out_blocks, batched at the end ----
    edge_scatter7_k<<<dim3(NEDGES, 7), HD>>>(rbf, out_rbf_w, XSAVE, ei, ATOM7);
    gemm_tf32<<<gA7, 256>>>(ATOM7, out_lins_w + 0 * HD * HD, out_lins_b + 0 * HD,
                            nullptr, nullptr, ATOM7B, NATOMS, HD, HD, 1, 0,
                            (size_t)NATOMS * HD, (size_t)3 * HD * HD, (size_t)3 * HD,
                            (size_t)NATOMS * HD);
    gemm_tf32<<<gA7, 256>>>(ATOM7B, out_lins_w + 1 * HD * HD, out_lins_b + 1 * HD,
                            nullptr, nullptr, ATOM7, NATOMS, HD, HD, 1, 0,
                            (size_t)NATOMS * HD, (size_t)3 * HD * HD, (size_t)3 * HD,
                            (size_t)NATOMS * HD);
    gemm_tf32<<<gA7, 256>>>(ATOM7, out_lins_w + 2 * HD * HD, out_lins_b + 2 * HD,
                            nullptr, nullptr, ATOM7B, NATOMS, HD, HD, 1, 0,
                            (size_t)NATOMS * HD, (size_t)3 * HD * HD, (size_t)3 * HD,
                            (size_t)NATOMS * HD);
    dot7_k<<<dim3((NATOMS + 7) / 8, 7), 256>>>(ATOM7B, out_w, batch, out);
}